// round 7
// baseline (speedup 1.0000x reference)
#include <cuda_runtime.h>
#include <cuda_bf16.h>
#include <mma.h>
#include <cstdint>

using namespace nvcuda;

// Problem dims
#define Bb     64
#define Nn     512
#define Tt     (Bb*Nn)        // 32768 tokens
#define DX     128
#define DIN    256
#define Hh     4096
#define Rr     1024

// GEMM tiling
#define BM 128
#define BN 128
#define BK 32

// ---------------- device scratch (identical set to the PASSING R2) ----------
__device__ float g_h1[(size_t)Tt * Hh];     // 512 MB: layer-1 raw matmul (pre-bias/relu)
__device__ float g_h2sum[(size_t)Bb * Hh];  // per-batch masked sum of h2
__device__ float g_maskf[Tt];               // normalized mask (0/1 fp32)
__device__ float g_cnt[Bb];                 // per-batch counts (>=1)
__device__ int   g_mtype;                   // 0=u8, 1=i32, 2=f32

// ---------------- mask dtype detection (verbatim from passing R2) -----------
__global__ void detect_mask_kernel(const unsigned int* m) {
    unsigned w0 = m[0], w1 = m[512], w2 = m[1024], w3 = m[1536];
    int t;
    if (w0 == 0x3F800000u && w1 == 0x3F800000u && w2 == 0x3F800000u && w3 == 0x3F800000u)
        t = 2;
    else if (w0 <= 1u && w1 <= 1u && w2 <= 1u && w3 <= 1u)
        t = 1;
    else
        t = 0;
    g_mtype = t;
}

__global__ void normalize_mask_kernel(const void* mask) {
    __shared__ float red[512];
    int b = blockIdx.x, n = threadIdx.x;
    int t = g_mtype;
    float v;
    size_t idx = (size_t)b * Nn + n;
    if (t == 0)      v = ((const unsigned char*)mask)[idx] ? 1.f : 0.f;
    else if (t == 1) v = ((const int*)mask)[idx] ? 1.f : 0.f;
    else             v = (((const float*)mask)[idx] != 0.f) ? 1.f : 0.f;
    g_maskf[idx] = v;
    red[n] = v;
    __syncthreads();
    for (int s = 256; s > 0; s >>= 1) {
        if (n < s) red[n] += red[n + s];
        __syncthreads();
    }
    if (n == 0) g_cnt[b] = fmaxf(red[0], 1.f);
    #pragma unroll
    for (int j = 0; j < 8; j++)
        g_h2sum[(size_t)b * Hh + n + 512 * j] = 0.f;
}

// ---------------- bf16 split helper ------------------------------------------
__device__ __forceinline__ void split2(float f0, float f1, uint32_t& hi, uint32_t& lo) {
    __nv_bfloat16 h0 = __float2bfloat16(f0), h1 = __float2bfloat16(f1);
    __nv_bfloat16 l0 = __float2bfloat16(f0 - __bfloat162float(h0));
    __nv_bfloat16 l1 = __float2bfloat16(f1 - __bfloat162float(h1));
    hi = (uint32_t)__bfloat16_as_ushort(h0) | ((uint32_t)__bfloat16_as_ushort(h1) << 16);
    lo = (uint32_t)__bfloat16_as_ushort(l0) | ((uint32_t)__bfloat16_as_ushort(l1) << 16);
}

// ============================================================================
// WMMA GEMM with in-register fp32 -> bf16 hi/lo split (3-MMA compensated).
//   D[BM,BN] = A[BM,K] @ W[K,BN]            (W row-major [K][Hh], no transpose)
// G1: A = concat(x,y) fp32; epilogue stores RAW acc to g_h1 (fp32).
// !G1: A = relu(g_h1 + b1) (bias+relu folded into A conversion);
//      epilogue = bias2+relu+mask-weighted column sum into g_h2sum.
// 8 warps, warp tile 32x64 (2x4 m16n16k16 frags), static smem only (~33KB),
// register-prefetch double buffering of global loads. No cp.async, no dynamic
// smem, no new statics — only new element vs passing R2 is wmma itself.
// ============================================================================
template<int KTOT, bool G1>
__global__ __launch_bounds__(256)
void wmma_gemm_kernel(const float* __restrict__ Ax, const float* __restrict__ Ay,
                      const float* __restrict__ W,  const float* __restrict__ abias,
                      const float* __restrict__ bias) {
    constexpr int NCH = KTOT / BK;
    const int n0 = blockIdx.x * BN;
    const int t0 = blockIdx.y * BM;
    if (g_maskf[t0] == 0.f) return;        // prefix mask: whole token tile dead

    const float* __restrict__ Asrc = G1 ? Ax : (const float*)g_h1;

    // manual carve of one static smem block (guaranteed contiguity)
    __shared__ __align__(16) char smraw[33280];
    __nv_bfloat16* sAh = (__nv_bfloat16*)(smraw);            // [128][32] m x k
    __nv_bfloat16* sAl = (__nv_bfloat16*)(smraw + 8192);
    __nv_bfloat16* sBh = (__nv_bfloat16*)(smraw + 16384);    // [32][128] k x n
    __nv_bfloat16* sBl = (__nv_bfloat16*)(smraw + 24576);
    float*         scol = (float*)(smraw + 32768);           // [128]

    const int tid  = threadIdx.x;
    const int wid  = tid >> 5;
    const int lane = tid & 31;
    const int wm   = wid >> 1;             // 0..3 (m, 32 rows each)
    const int wn   = wid & 1;              // 0..1 (n, 64 cols each)

    if (!G1 && tid < BN) scol[tid] = 0.f;  // ordered by later __syncthreads

    wmma::fragment<wmma::accumulator, 16, 16, 16, float> acc[2][4];
    #pragma unroll
    for (int mi = 0; mi < 2; mi++)
        #pragma unroll
        for (int nj = 0; nj < 4; nj++)
            wmma::fill_fragment(acc[mi][nj], 0.f);

    float4 ra[4], rb[4];

    auto loadA = [&](int k0) {
        #pragma unroll
        for (int i = 0; i < 4; i++) {
            int idx = tid + i * 256;
            int r = idx >> 3, c = idx & 7;
            int k = k0 + c * 4;
            const float* p;
            if (G1) p = (k < DX) ? (Ax + (size_t)(t0 + r) * DX + k)
                                 : (Ay + (size_t)(t0 + r) * DX + (k - DX));
            else    p = Asrc + (size_t)(t0 + r) * KTOT + k;
            ra[i] = *(const float4*)p;
        }
    };
    auto loadB = [&](int k0) {
        #pragma unroll
        for (int i = 0; i < 4; i++) {
            int idx = tid + i * 256;
            int r = idx >> 5, c = idx & 31;
            rb[i] = *(const float4*)(W + (size_t)(k0 + r) * Hh + n0 + c * 4);
        }
    };
    auto storeAB = [&](int k0) {
        #pragma unroll
        for (int i = 0; i < 4; i++) {
            int idx = tid + i * 256;
            { // A: apply (bias1 + relu) when this is layer 2
                int r = idx >> 3, c = idx & 7;
                float v0 = ra[i].x, v1 = ra[i].y, v2 = ra[i].z, v3 = ra[i].w;
                if (!G1) {
                    int k = k0 + c * 4;
                    v0 = fmaxf(v0 + abias[k],     0.f);
                    v1 = fmaxf(v1 + abias[k + 1], 0.f);
                    v2 = fmaxf(v2 + abias[k + 2], 0.f);
                    v3 = fmaxf(v3 + abias[k + 3], 0.f);
                }
                uint32_t h0, l0, h1, l1;
                split2(v0, v1, h0, l0);
                split2(v2, v3, h1, l1);
                *(uint2*)(sAh + r * BK + c * 4) = make_uint2(h0, h1);
                *(uint2*)(sAl + r * BK + c * 4) = make_uint2(l0, l1);
            }
            { // B
                int r = idx >> 5, c = idx & 31;
                uint32_t h0, l0, h1, l1;
                split2(rb[i].x, rb[i].y, h0, l0);
                split2(rb[i].z, rb[i].w, h1, l1);
                *(uint2*)(sBh + r * BN + c * 4) = make_uint2(h0, h1);
                *(uint2*)(sBl + r * BN + c * 4) = make_uint2(l0, l1);
            }
        }
    };

    loadA(0); loadB(0);

    for (int ch = 0; ch < NCH; ch++) {
        __syncthreads();                   // previous chunk's MMA reads done
        storeAB(ch * BK);
        __syncthreads();
        if (ch + 1 < NCH) { loadA((ch + 1) * BK); loadB((ch + 1) * BK); }

        #pragma unroll
        for (int kk = 0; kk < 2; kk++) {   // two k16 steps per BK=32
            wmma::fragment<wmma::matrix_a, 16, 16, 16, __nv_bfloat16, wmma::row_major> ah[2], al[2];
            #pragma unroll
            for (int mi = 0; mi < 2; mi++) {
                int ro = (wm * 32 + mi * 16) * BK + kk * 16;
                wmma::load_matrix_sync(ah[mi], sAh + ro, BK);
                wmma::load_matrix_sync(al[mi], sAl + ro, BK);
            }
            wmma::fragment<wmma::matrix_b, 16, 16, 16, __nv_bfloat16, wmma::row_major> bh[4], bl[4];
            #pragma unroll
            for (int nj = 0; nj < 4; nj++) {
                int ro = (kk * 16) * BN + wn * 64 + nj * 16;
                wmma::load_matrix_sync(bh[nj], sBh + ro, BN);
                wmma::load_matrix_sync(bl[nj], sBl + ro, BN);
            }
            #pragma unroll
            for (int mi = 0; mi < 2; mi++)
                #pragma unroll
                for (int nj = 0; nj < 4; nj++) {
                    wmma::mma_sync(acc[mi][nj], ah[mi], bh[nj], acc[mi][nj]);
                    wmma::mma_sync(acc[mi][nj], ah[mi], bl[nj], acc[mi][nj]);
                    wmma::mma_sync(acc[mi][nj], al[mi], bh[nj], acc[mi][nj]);
                }
        }
    }

    __syncthreads();                       // all MMA done; smem tiles reusable

    if (G1) {
        // store RAW matmul to g_h1 (bias+relu folded into layer-2 A conversion)
        #pragma unroll
        for (int mi = 0; mi < 2; mi++)
            #pragma unroll
            for (int nj = 0; nj < 4; nj++)
                wmma::store_matrix_sync(
                    g_h1 + (size_t)(t0 + wm * 32 + mi * 16) * Hh + n0 + wn * 64 + nj * 16,
                    acc[mi][nj], Hh, wmma::mem_row_major);
    } else {
        // per-warp 16x16 f32 scratch inside the (now free) tile region
        float* scr = (float*)smraw + wid * (16 * 20);   // 1280B/warp, 10240B total
        const int cc = lane & 15, hh = lane >> 4;
        #pragma unroll
        for (int nj = 0; nj < 4; nj++) {
            int colg = n0 + wn * 64 + nj * 16 + cc;
            float bv = bias[colg];
            float s = 0.f;
            #pragma unroll
            for (int mi = 0; mi < 2; mi++) {
                wmma::store_matrix_sync(scr, acc[mi][nj], 20, wmma::mem_row_major);
                __syncwarp();
                #pragma unroll
                for (int j = 0; j < 8; j++) {
                    int row = t0 + wm * 32 + mi * 16 + hh * 8 + j;
                    s += g_maskf[row] * fmaxf(scr[(hh * 8 + j) * 20 + cc] + bv, 0.f);
                }
                __syncwarp();
            }
            s += __shfl_down_sync(0xffffffffu, s, 16);
            if (lane < 16) atomicAdd(&scol[wn * 64 + nj * 16 + lane], s);
        }
        __syncthreads();
        if (tid < BN) {
            int bb = t0 / Nn;              // 128-token tile lies in one batch
            atomicAdd(&g_h2sum[(size_t)bb * Hh + n0 + tid], scol[tid]);
        }
    }
}

// ============================================================================
// Layer 3 (tiny): out = (h2sum/count) @ W3 + b3      M=64, K=4096, N=1024
// ============================================================================
__global__ void out_init_kernel(float* __restrict__ out, const float* __restrict__ b3) {
    int b = blockIdx.x, r = threadIdx.x;
    #pragma unroll
    for (int j = 0; j < 4; j++)
        out[(size_t)b * Rr + r + 256 * j] = b3[r + 256 * j];
}

__global__ __launch_bounds__(256)
void out_gemm_kernel(const float* __restrict__ W3, float* __restrict__ out) {
    __shared__ float As[Bb * 128];
    int rt = blockIdx.x * 128;
    int k0 = blockIdx.y * 128;
    int tid = threadIdx.x;

    #pragma unroll
    for (int l = 0; l < 32; l++) {
        int idx = tid + l * 256;
        int b = idx >> 7, k = idx & 127;
        As[b * 128 + k] = g_h2sum[(size_t)b * Hh + k0 + k] / g_cnt[b];
    }
    __syncthreads();

    int c = tid & 127, bg = tid >> 7;
    float acc[32];
    #pragma unroll
    for (int i = 0; i < 32; i++) acc[i] = 0.f;

    for (int k = 0; k < 128; k++) {
        float w = W3[(size_t)(k0 + k) * Rr + rt + c];
        #pragma unroll
        for (int i = 0; i < 32; i++)
            acc[i] += As[(bg * 32 + i) * 128 + k] * w;
    }
    #pragma unroll
    for (int i = 0; i < 32; i++)
        atomicAdd(&out[(size_t)(bg * 32 + i) * Rr + rt + c], acc[i]);
}

// ============================================================================
extern "C" void kernel_launch(void* const* d_in, const int* in_sizes, int n_in,
                              void* d_out, int out_size) {
    const float* x  = (const float*)d_in[0];
    const float* y  = (const float*)d_in[1];
    const void*  mk = d_in[2];
    const float* W1 = (const float*)d_in[3];
    const float* b1 = (const float*)d_in[4];
    const float* W2 = (const float*)d_in[5];
    const float* b2 = (const float*)d_in[6];
    const float* W3 = (const float*)d_in[7];
    const float* b3 = (const float*)d_in[8];
    float* out = (float*)d_out;

    detect_mask_kernel<<<1, 1>>>((const unsigned int*)mk);
    normalize_mask_kernel<<<Bb, Nn>>>(mk);
    // layer 1: raw matmul -> g_h1 (bias1+relu deferred to layer-2 A conversion)
    wmma_gemm_kernel<DIN, true><<<dim3(Hh / BN, Tt / BM), 256>>>(x, y, W1, nullptr, nullptr);
    // layer 2: A = relu(g_h1 + b1); epilogue bias2+relu+masked colsum
    wmma_gemm_kernel<Hh, false><<<dim3(Hh / BN, Tt / BM), 256>>>(nullptr, nullptr, W2, b1, b2);
    out_init_kernel<<<Bb, 256>>>(out, b3);
    out_gemm_kernel<<<dim3(Rr / 128, Hh / 128), 256>>>(W3, out);
}

// round 9
// speedup vs baseline: 1.8955x; 1.8955x over previous
#include <cuda_runtime.h>
#include <cuda_bf16.h>
#include <mma.h>
#include <cstdint>

using namespace nvcuda;

// Problem dims
#define Bb     64
#define Nn     512
#define Tt     (Bb*Nn)        // 32768 tokens
#define DX     128
#define DIN    256
#define Hh     4096
#define Rr     1024

// GEMM tiling
#define BM 128
#define BN 64
#define BK 32
#define SPA 40                 // A smem row stride (bf16 elems)
#define SPB 72                 // B smem row stride (bf16 elems)

// ---------------- device scratch (SAME footprint as passing R2/R7) ----------
// ONE 512MB static: h1 bf16 hi plane at [0], lo plane at [HOFF].
#define HOFF ((size_t)Tt * Hh)
__device__ __nv_bfloat16 g_h1s[2 * HOFF];   // 512 MB total
__device__ float g_h2sum[(size_t)Bb * Hh];
__device__ float g_maskf[Tt];
__device__ float g_cnt[Bb];
__device__ int   g_mtype;

// ---------------- mask dtype detection (verbatim, validated) ----------------
__global__ void detect_mask_kernel(const unsigned int* m) {
    unsigned w0 = m[0], w1 = m[512], w2 = m[1024], w3 = m[1536];
    int t;
    if (w0 == 0x3F800000u && w1 == 0x3F800000u && w2 == 0x3F800000u && w3 == 0x3F800000u)
        t = 2;
    else if (w0 <= 1u && w1 <= 1u && w2 <= 1u && w3 <= 1u)
        t = 1;
    else
        t = 0;
    g_mtype = t;
}

__global__ void normalize_mask_kernel(const void* mask) {
    __shared__ float red[512];
    int b = blockIdx.x, n = threadIdx.x;
    int t = g_mtype;
    float v;
    size_t idx = (size_t)b * Nn + n;
    if (t == 0)      v = ((const unsigned char*)mask)[idx] ? 1.f : 0.f;
    else if (t == 1) v = ((const int*)mask)[idx] ? 1.f : 0.f;
    else             v = (((const float*)mask)[idx] != 0.f) ? 1.f : 0.f;
    g_maskf[idx] = v;
    red[n] = v;
    __syncthreads();
    for (int s = 256; s > 0; s >>= 1) {
        if (n < s) red[n] += red[n + s];
        __syncthreads();
    }
    if (n == 0) g_cnt[b] = fmaxf(red[0], 1.f);
    #pragma unroll
    for (int j = 0; j < 8; j++)
        g_h2sum[(size_t)b * Hh + n + 512 * j] = 0.f;
}

// ---------------- bf16 split helpers -----------------------------------------
__device__ __forceinline__ void split1(float f, unsigned short& h, unsigned short& l) {
    __nv_bfloat16 hb = __float2bfloat16(f);
    __nv_bfloat16 lb = __float2bfloat16(f - __bfloat162float(hb));
    h = __bfloat16_as_ushort(hb);
    l = __bfloat16_as_ushort(lb);
}
__device__ __forceinline__ void split4(float4 v, uint2& hi, uint2& lo) {
    unsigned short h0, l0, h1, l1, h2, l2, h3, l3;
    split1(v.x, h0, l0); split1(v.y, h1, l1);
    split1(v.z, h2, l2); split1(v.w, h3, l3);
    hi = make_uint2((uint32_t)h0 | ((uint32_t)h1 << 16), (uint32_t)h2 | ((uint32_t)h3 << 16));
    lo = make_uint2((uint32_t)l0 | ((uint32_t)l1 << 16), (uint32_t)l2 | ((uint32_t)l3 << 16));
}

// ============================================================================
// WMMA GEMM, bf16 hi/lo 3-MMA compensated, F32 accum. 8 warps as 4(m) x 2(n),
// warp tile 32x32, BM=128 BN=64 BK=32, 2 CTAs/SM.
// G1 (layer1, K=256): A = concat(x,y) fp32 (in-register split);
//     epilogue = bias1+relu -> bf16 hi/lo -> g_h1s planes.
// G2 (layer2, K=4096): A = g_h1s pre-split bf16; B = W2 fp32 (in-register
//     split); epilogue = bias2+relu -> mask-weighted column sum -> g_h2sum.
// ============================================================================
template<bool G1>
__global__ __launch_bounds__(256, 2)
void gemm_kernel(const float* __restrict__ Ax, const float* __restrict__ Ay,
                 const float* __restrict__ W, const float* __restrict__ bias) {
    constexpr int KTOT = G1 ? DIN : Hh;
    constexpr int NCH  = KTOT / BK;
    const int n0 = blockIdx.x * BN;
    const int t0 = blockIdx.y * BM;
    if (g_maskf[t0] == 0.f) return;        // prefix mask: whole token tile dead

    __shared__ __align__(16) __nv_bfloat16 sAh[BM * SPA];   // 10240 B
    __shared__ __align__(16) __nv_bfloat16 sAl[BM * SPA];
    __shared__ __align__(16) __nv_bfloat16 sBh[BK * SPB];   // 4608 B
    __shared__ __align__(16) __nv_bfloat16 sBl[BK * SPB];
    __shared__ float scol[BN];

    const int tid  = threadIdx.x;
    const int wid  = tid >> 5;
    const int lane = tid & 31;
    const int wm   = wid >> 1;             // 0..3 (m, 32 rows)
    const int wn   = wid & 1;              // 0..1 (n, 32 cols)

    if (!G1 && tid < BN) scol[tid] = 0.f;  // ordered by loop's first barrier

    wmma::fragment<wmma::accumulator, 16, 16, 16, float> acc[2][2];
    #pragma unroll
    for (int mi = 0; mi < 2; mi++)
        #pragma unroll
        for (int nj = 0; nj < 2; nj++)
            wmma::fill_fragment(acc[mi][nj], 0.f);

    // ---- prefetch registers ----
    float4 fa[4];                          // G1 A: 128 rows x 8 float4
    uint4  ua_h[2], ua_l[2];               // G2 A: pre-split bf16
    float4 fb[2];                          // B: 32 rows x 16 float4

    const int a8r = tid >> 3, a8c = tid & 7;      // G1 A map (4 iters)
    const int a2r = tid >> 1, a2c = (tid & 1) * 2;// G2 A map (16B chunks)
    const int b_r = tid >> 4, b_c = tid & 15;     // B map (2 iters)

    auto prefetch = [&](int k0) {
        if (G1) {
            #pragma unroll
            for (int i = 0; i < 4; i++) {
                int r = a8r + i * 32;
                int k = k0 + a8c * 4;
                const float* p = (k < DX) ? (Ax + (size_t)(t0 + r) * DX + k)
                                          : (Ay + (size_t)(t0 + r) * DX + (k - DX));
                fa[i] = *(const float4*)p;
            }
        } else {
            const __nv_bfloat16* ph = g_h1s + (size_t)(t0 + a2r) * Hh + k0 + a2c * 8;
            const __nv_bfloat16* pl = ph + HOFF;
            ua_h[0] = *(const uint4*)ph;       ua_h[1] = *(const uint4*)(ph + 8);
            ua_l[0] = *(const uint4*)pl;       ua_l[1] = *(const uint4*)(pl + 8);
        }
        #pragma unroll
        for (int i = 0; i < 2; i++) {
            int r = b_r + i * 16;
            fb[i] = *(const float4*)(W + (size_t)(k0 + r) * Hh + n0 + b_c * 4);
        }
    };
    auto stage = [&]() {
        if (G1) {
            #pragma unroll
            for (int i = 0; i < 4; i++) {
                int r = a8r + i * 32;
                uint2 h, l;
                split4(fa[i], h, l);
                *(uint2*)(sAh + r * SPA + a8c * 4) = h;
                *(uint2*)(sAl + r * SPA + a8c * 4) = l;
            }
        } else {
            *(uint4*)(sAh + a2r * SPA + a2c * 8)       = ua_h[0];
            *(uint4*)(sAh + a2r * SPA + (a2c + 1) * 8) = ua_h[1];
            *(uint4*)(sAl + a2r * SPA + a2c * 8)       = ua_l[0];
            *(uint4*)(sAl + a2r * SPA + (a2c + 1) * 8) = ua_l[1];
        }
        #pragma unroll
        for (int i = 0; i < 2; i++) {
            int r = b_r + i * 16;
            uint2 h, l;
            split4(fb[i], h, l);
            *(uint2*)(sBh + r * SPB + b_c * 4) = h;
            *(uint2*)(sBl + r * SPB + b_c * 4) = l;
        }
    };

    prefetch(0);

    for (int ch = 0; ch < NCH; ch++) {
        __syncthreads();                   // previous chunk's MMA reads done
        stage();
        __syncthreads();
        if (ch + 1 < NCH) prefetch((ch + 1) * BK);

        #pragma unroll
        for (int kk = 0; kk < 2; kk++) {
            wmma::fragment<wmma::matrix_a, 16, 16, 16, __nv_bfloat16, wmma::row_major> ah[2], al[2];
            #pragma unroll
            for (int mi = 0; mi < 2; mi++) {
                int ro = (wm * 32 + mi * 16) * SPA + kk * 16;
                wmma::load_matrix_sync(ah[mi], sAh + ro, SPA);
                wmma::load_matrix_sync(al[mi], sAl + ro, SPA);
            }
            wmma::fragment<wmma::matrix_b, 16, 16, 16, __nv_bfloat16, wmma::row_major> bh[2], bl[2];
            #pragma unroll
            for (int nj = 0; nj < 2; nj++) {
                int ro = (kk * 16) * SPB + wn * 32 + nj * 16;
                wmma::load_matrix_sync(bh[nj], sBh + ro, SPB);
                wmma::load_matrix_sync(bl[nj], sBl + ro, SPB);
            }
            #pragma unroll
            for (int mi = 0; mi < 2; mi++)
                #pragma unroll
                for (int nj = 0; nj < 2; nj++) {
                    wmma::mma_sync(acc[mi][nj], ah[mi], bh[nj], acc[mi][nj]);
                    wmma::mma_sync(acc[mi][nj], ah[mi], bl[nj], acc[mi][nj]);
                    wmma::mma_sync(acc[mi][nj], al[mi], bh[nj], acc[mi][nj]);
                }
        }
    }

    __syncthreads();                       // all MMA done; smem reusable

    // per-warp 16x16 f32 scratch carved from sAh (8 x 1280B = 10240B exact)
    float* scr = (float*)sAh + wid * (16 * 20);

    if (G1) {
        const int tr   = lane >> 1;        // tile row 0..15
        const int half = lane & 1;         // 8-col half
        #pragma unroll
        for (int mi = 0; mi < 2; mi++)
            #pragma unroll
            for (int nj = 0; nj < 2; nj++) {
                wmma::store_matrix_sync(scr, acc[mi][nj], 20, wmma::mem_row_major);
                __syncwarp();
                int colb = n0 + wn * 32 + nj * 16 + half * 8;
                int row  = t0 + wm * 32 + mi * 16 + tr;
                uint32_t ph[4], pl[4];
                #pragma unroll
                for (int q = 0; q < 4; q++) {
                    float f0 = fmaxf(scr[tr * 20 + half * 8 + 2 * q]     + bias[colb + 2 * q],     0.f);
                    float f1 = fmaxf(scr[tr * 20 + half * 8 + 2 * q + 1] + bias[colb + 2 * q + 1], 0.f);
                    unsigned short h0, l0, h1, l1;
                    split1(f0, h0, l0);
                    split1(f1, h1, l1);
                    ph[q] = (uint32_t)h0 | ((uint32_t)h1 << 16);
                    pl[q] = (uint32_t)l0 | ((uint32_t)l1 << 16);
                }
                *(uint4*)(g_h1s + (size_t)row * Hh + colb)        = make_uint4(ph[0], ph[1], ph[2], ph[3]);
                *(uint4*)(g_h1s + HOFF + (size_t)row * Hh + colb) = make_uint4(pl[0], pl[1], pl[2], pl[3]);
                __syncwarp();
            }
    } else {
        const int cc = lane & 15, hh = lane >> 4;
        #pragma unroll
        for (int nj = 0; nj < 2; nj++) {
            int colg = n0 + wn * 32 + nj * 16 + cc;
            float bv = bias[colg];
            float s = 0.f;
            #pragma unroll
            for (int mi = 0; mi < 2; mi++) {
                wmma::store_matrix_sync(scr, acc[mi][nj], 20, wmma::mem_row_major);
                __syncwarp();
                #pragma unroll
                for (int j = 0; j < 8; j++) {
                    int row = t0 + wm * 32 + mi * 16 + hh * 8 + j;
                    s += g_maskf[row] * fmaxf(scr[(hh * 8 + j) * 20 + cc] + bv, 0.f);
                }
                __syncwarp();
            }
            s += __shfl_down_sync(0xffffffffu, s, 16);
            if (lane < 16) atomicAdd(&scol[wn * 32 + nj * 16 + lane], s);
        }
        __syncthreads();
        if (tid < BN) {
            int bb = t0 / Nn;              // 128-token tile lies in one batch
            atomicAdd(&g_h2sum[(size_t)bb * Hh + n0 + tid], scol[tid]);
        }
    }
}

// ============================================================================
// Layer 3 (tiny): out = (h2sum/count) @ W3 + b3      M=64, K=4096, N=1024
// ============================================================================
__global__ void out_init_kernel(float* __restrict__ out, const float* __restrict__ b3) {
    int b = blockIdx.x, r = threadIdx.x;
    #pragma unroll
    for (int j = 0; j < 4; j++)
        out[(size_t)b * Rr + r + 256 * j] = b3[r + 256 * j];
}

__global__ __launch_bounds__(256)
void out_gemm_kernel(const float* __restrict__ W3, float* __restrict__ out) {
    __shared__ float As[Bb * 128];
    int rt = blockIdx.x * 128;
    int k0 = blockIdx.y * 128;
    int tid = threadIdx.x;

    #pragma unroll
    for (int l = 0; l < 32; l++) {
        int idx = tid + l * 256;
        int b = idx >> 7, k = idx & 127;
        As[b * 128 + k] = g_h2sum[(size_t)b * Hh + k0 + k] / g_cnt[b];
    }
    __syncthreads();

    int c = tid & 127, bg = tid >> 7;
    float acc[32];
    #pragma unroll
    for (int i = 0; i < 32; i++) acc[i] = 0.f;

    for (int k = 0; k < 128; k++) {
        float w = W3[(size_t)(k0 + k) * Rr + rt + c];
        #pragma unroll
        for (int i = 0; i < 32; i++)
            acc[i] += As[(bg * 32 + i) * 128 + k] * w;
    }
    #pragma unroll
    for (int i = 0; i < 32; i++)
        atomicAdd(&out[(size_t)(bg * 32 + i) * Rr + rt + c], acc[i]);
}

// ============================================================================
extern "C" void kernel_launch(void* const* d_in, const int* in_sizes, int n_in,
                              void* d_out, int out_size) {
    const float* x  = (const float*)d_in[0];
    const float* y  = (const float*)d_in[1];
    const void*  mk = d_in[2];
    const float* W1 = (const float*)d_in[3];
    const float* b1 = (const float*)d_in[4];
    const float* W2 = (const float*)d_in[5];
    const float* b2 = (const float*)d_in[6];
    const float* W3 = (const float*)d_in[7];
    const float* b3 = (const float*)d_in[8];
    float* out = (float*)d_out;

    detect_mask_kernel<<<1, 1>>>((const unsigned int*)mk);
    normalize_mask_kernel<<<Bb, Nn>>>(mk);
    gemm_kernel<true><<<dim3(Hh / BN, Tt / BM), 256>>>(x, y, W1, b1);
    gemm_kernel<false><<<dim3(Hh / BN, Tt / BM), 256>>>(nullptr, nullptr, W2, b2);
    out_init_kernel<<<Bb, 256>>>(out, b3);
    out_gemm_kernel<<<dim3(Rr / 128, Hh / 128), 256>>>(W3, out);
}

// round 10
// speedup vs baseline: 2.2696x; 1.1973x over previous
#include <cuda_runtime.h>
#include <cuda_bf16.h>
#include <mma.h>
#include <cstdint>

using namespace nvcuda;

// Problem dims
#define Bb     64
#define Nn     512
#define Tt     (Bb*Nn)        // 32768 tokens
#define DX     128
#define DIN    256
#define Hh     4096
#define Rr     1024

// GEMM tiling: CTA 128x128, 8 warps as 4(m) x 2(n), warp tile 32x64
#define BM 128
#define BN 128
#define BK 32
#define SPA 40                 // A smem row stride (bf16 elems)
#define SPB 136                // B smem row stride (bf16 elems)

// ---------------- device scratch (validated footprint) ----------------------
#define HOFF ((size_t)Tt * Hh)
__device__ __nv_bfloat16 g_h1s[2 * HOFF];   // 512 MB: h1 bf16 hi plane, lo plane
__device__ float g_h2sum[(size_t)Bb * Hh];
__device__ float g_maskf[Tt];
__device__ float g_cnt[Bb];
__device__ int   g_mtype;

// ---------------- mask dtype detection (verbatim, validated) ----------------
__global__ void detect_mask_kernel(const unsigned int* m) {
    unsigned w0 = m[0], w1 = m[512], w2 = m[1024], w3 = m[1536];
    int t;
    if (w0 == 0x3F800000u && w1 == 0x3F800000u && w2 == 0x3F800000u && w3 == 0x3F800000u)
        t = 2;
    else if (w0 <= 1u && w1 <= 1u && w2 <= 1u && w3 <= 1u)
        t = 1;
    else
        t = 0;
    g_mtype = t;
}

__global__ void normalize_mask_kernel(const void* mask) {
    __shared__ float red[512];
    int b = blockIdx.x, n = threadIdx.x;
    int t = g_mtype;
    float v;
    size_t idx = (size_t)b * Nn + n;
    if (t == 0)      v = ((const unsigned char*)mask)[idx] ? 1.f : 0.f;
    else if (t == 1) v = ((const int*)mask)[idx] ? 1.f : 0.f;
    else             v = (((const float*)mask)[idx] != 0.f) ? 1.f : 0.f;
    g_maskf[idx] = v;
    red[n] = v;
    __syncthreads();
    for (int s = 256; s > 0; s >>= 1) {
        if (n < s) red[n] += red[n + s];
        __syncthreads();
    }
    if (n == 0) g_cnt[b] = fmaxf(red[0], 1.f);
    #pragma unroll
    for (int j = 0; j < 8; j++)
        g_h2sum[(size_t)b * Hh + n + 512 * j] = 0.f;
}

// ---------------- bf16 split helpers -----------------------------------------
__device__ __forceinline__ void split1(float f, unsigned short& h, unsigned short& l) {
    __nv_bfloat16 hb = __float2bfloat16(f);
    __nv_bfloat16 lb = __float2bfloat16(f - __bfloat162float(hb));
    h = __bfloat16_as_ushort(hb);
    l = __bfloat16_as_ushort(lb);
}
__device__ __forceinline__ void split4(float4 v, uint2& hi, uint2& lo) {
    unsigned short h0, l0, h1, l1, h2, l2, h3, l3;
    split1(v.x, h0, l0); split1(v.y, h1, l1);
    split1(v.z, h2, l2); split1(v.w, h3, l3);
    hi = make_uint2((uint32_t)h0 | ((uint32_t)h1 << 16), (uint32_t)h2 | ((uint32_t)h3 << 16));
    lo = make_uint2((uint32_t)l0 | ((uint32_t)l1 << 16), (uint32_t)l2 | ((uint32_t)l3 << 16));
}

// ============================================================================
// WMMA GEMM, bf16 hi/lo 3-MMA compensated, F32 accum.
// CTA 128x128, 8 warps 4(m)x2(n), warp tile 32x64 (2x4 frags), BK=32,
// 2 CTAs/SM, direct LDG->split->STS staging (no register prefetch; latency
// covered by co-resident CTA). Two barriers per chunk (validated structure).
// G1 (K=256): A = concat(x,y) fp32 split in stage; epilogue bias1+relu ->
//     bf16 hi/lo -> g_h1s planes.
// G2 (K=4096): A = g_h1s pre-split; B = W2 fp32 split in stage; epilogue
//     bias2+relu -> mask-weighted column sum -> g_h2sum.
// ============================================================================
template<bool G1>
__global__ __launch_bounds__(256, 2)
void gemm_kernel(const float* __restrict__ Ax, const float* __restrict__ Ay,
                 const float* __restrict__ W, const float* __restrict__ bias) {
    constexpr int KTOT = G1 ? DIN : Hh;
    constexpr int NCH  = KTOT / BK;
    const int n0 = blockIdx.x * BN;
    const int t0 = blockIdx.y * BM;
    if (g_maskf[t0] == 0.f) return;        // prefix mask: whole token tile dead

    __shared__ __align__(16) __nv_bfloat16 sAh[BM * SPA];   // 10240 B
    __shared__ __align__(16) __nv_bfloat16 sAl[BM * SPA];
    __shared__ __align__(16) __nv_bfloat16 sBh[BK * SPB];   // 8704 B
    __shared__ __align__(16) __nv_bfloat16 sBl[BK * SPB];
    __shared__ float scol[BN];

    const int tid  = threadIdx.x;
    const int wid  = tid >> 5;
    const int lane = tid & 31;
    const int wm   = wid >> 1;             // 0..3 (m, 32 rows)
    const int wn   = wid & 1;              // 0..1 (n, 64 cols)

    if (!G1 && tid < BN) scol[tid] = 0.f;  // ordered by loop's first barrier

    wmma::fragment<wmma::accumulator, 16, 16, 16, float> acc[2][4];
    #pragma unroll
    for (int mi = 0; mi < 2; mi++)
        #pragma unroll
        for (int nj = 0; nj < 4; nj++)
            wmma::fill_fragment(acc[mi][nj], 0.f);

    // stage index maps
    const int a8r = tid >> 3, a8c = tid & 7;       // G1 A: fp32, 4 iters of 32 rows
    const int a2r = tid >> 1, a2c = (tid & 1) * 2; // G2 A: pre-split, 16B chunks

    // stage: LDG -> (split) -> STS, latency exposed (hidden by 2-CTA overlap)
    auto stage = [&](int k0) {
        if (G1) {
            #pragma unroll
            for (int i = 0; i < 4; i++) {
                int r = a8r + i * 32;
                int k = k0 + a8c * 4;
                const float* p = (k < DX) ? (Ax + (size_t)(t0 + r) * DX + k)
                                          : (Ay + (size_t)(t0 + r) * DX + (k - DX));
                uint2 h, l;
                split4(*(const float4*)p, h, l);
                *(uint2*)(sAh + r * SPA + a8c * 4) = h;
                *(uint2*)(sAl + r * SPA + a8c * 4) = l;
            }
        } else {
            const __nv_bfloat16* ph = g_h1s + (size_t)(t0 + a2r) * Hh + k0 + a2c * 8;
            const __nv_bfloat16* pl = ph + HOFF;
            *(uint4*)(sAh + a2r * SPA + a2c * 8)       = *(const uint4*)ph;
            *(uint4*)(sAh + a2r * SPA + (a2c + 1) * 8) = *(const uint4*)(ph + 8);
            *(uint4*)(sAl + a2r * SPA + a2c * 8)       = *(const uint4*)pl;
            *(uint4*)(sAl + a2r * SPA + (a2c + 1) * 8) = *(const uint4*)(pl + 8);
        }
        // B: 32 rows x 128 cols fp32 = 1024 float4, 4 per thread
        #pragma unroll
        for (int i = 0; i < 4; i++) {
            int idx = tid + i * 256;
            int r = idx >> 5, c = idx & 31;
            uint2 h, l;
            split4(*(const float4*)(W + (size_t)(k0 + r) * Hh + n0 + c * 4), h, l);
            *(uint2*)(sBh + r * SPB + c * 4) = h;
            *(uint2*)(sBl + r * SPB + c * 4) = l;
        }
    };

    for (int ch = 0; ch < NCH; ch++) {
        __syncthreads();                   // previous chunk's MMA reads done
        stage(ch * BK);
        __syncthreads();

        #pragma unroll
        for (int kk = 0; kk < 2; kk++) {
            wmma::fragment<wmma::matrix_a, 16, 16, 16, __nv_bfloat16, wmma::row_major> ah[2], al[2];
            #pragma unroll
            for (int mi = 0; mi < 2; mi++) {
                int ro = (wm * 32 + mi * 16) * SPA + kk * 16;
                wmma::load_matrix_sync(ah[mi], sAh + ro, SPA);
                wmma::load_matrix_sync(al[mi], sAl + ro, SPA);
            }
            #pragma unroll
            for (int nj = 0; nj < 4; nj++) {
                wmma::fragment<wmma::matrix_b, 16, 16, 16, __nv_bfloat16, wmma::row_major> bh, bl;
                int ro = (kk * 16) * SPB + wn * 64 + nj * 16;
                wmma::load_matrix_sync(bh, sBh + ro, SPB);
                wmma::load_matrix_sync(bl, sBl + ro, SPB);
                #pragma unroll
                for (int mi = 0; mi < 2; mi++) {
                    wmma::mma_sync(acc[mi][nj], ah[mi], bh, acc[mi][nj]);
                    wmma::mma_sync(acc[mi][nj], ah[mi], bl, acc[mi][nj]);
                    wmma::mma_sync(acc[mi][nj], al[mi], bh, acc[mi][nj]);
                }
            }
        }
    }

    __syncthreads();                       // all MMA done; smem reusable

    // per-warp 16x16 f32 scratch carved from sAh (8 x 1280B = 10240B exact)
    float* scr = (float*)sAh + wid * (16 * 20);

    if (G1) {
        const int tr   = lane >> 1;        // tile row 0..15
        const int half = lane & 1;         // 8-col half
        #pragma unroll
        for (int mi = 0; mi < 2; mi++)
            #pragma unroll
            for (int nj = 0; nj < 4; nj++) {
                wmma::store_matrix_sync(scr, acc[mi][nj], 20, wmma::mem_row_major);
                __syncwarp();
                int colb = n0 + wn * 64 + nj * 16 + half * 8;
                int row  = t0 + wm * 32 + mi * 16 + tr;
                uint32_t ph[4], pl[4];
                #pragma unroll
                for (int q = 0; q < 4; q++) {
                    float f0 = fmaxf(scr[tr * 20 + half * 8 + 2 * q]     + bias[colb + 2 * q],     0.f);
                    float f1 = fmaxf(scr[tr * 20 + half * 8 + 2 * q + 1] + bias[colb + 2 * q + 1], 0.f);
                    unsigned short h0, l0, h1, l1;
                    split1(f0, h0, l0);
                    split1(f1, h1, l1);
                    ph[q] = (uint32_t)h0 | ((uint32_t)h1 << 16);
                    pl[q] = (uint32_t)l0 | ((uint32_t)l1 << 16);
                }
                *(uint4*)(g_h1s + (size_t)row * Hh + colb)        = make_uint4(ph[0], ph[1], ph[2], ph[3]);
                *(uint4*)(g_h1s + HOFF + (size_t)row * Hh + colb) = make_uint4(pl[0], pl[1], pl[2], pl[3]);
                __syncwarp();
            }
    } else {
        const int cc = lane & 15, hh = lane >> 4;
        #pragma unroll
        for (int nj = 0; nj < 4; nj++) {
            int colg = n0 + wn * 64 + nj * 16 + cc;
            float bv = bias[colg];
            float s = 0.f;
            #pragma unroll
            for (int mi = 0; mi < 2; mi++) {
                wmma::store_matrix_sync(scr, acc[mi][nj], 20, wmma::mem_row_major);
                __syncwarp();
                #pragma unroll
                for (int j = 0; j < 8; j++) {
                    int row = t0 + wm * 32 + mi * 16 + hh * 8 + j;
                    s += g_maskf[row] * fmaxf(scr[(hh * 8 + j) * 20 + cc] + bv, 0.f);
                }
                __syncwarp();
            }
            s += __shfl_down_sync(0xffffffffu, s, 16);
            if (lane < 16) atomicAdd(&scol[wn * 64 + nj * 16 + lane], s);
        }
        __syncthreads();
        if (tid < BN) {
            int bb = t0 / Nn;              // 128-token tile lies in one batch
            atomicAdd(&g_h2sum[(size_t)bb * Hh + n0 + tid], scol[tid]);
        }
    }
}

// ============================================================================
// Layer 3 (tiny): out = (h2sum/count) @ W3 + b3      M=64, K=4096, N=1024
// ============================================================================
__global__ void out_init_kernel(float* __restrict__ out, const float* __restrict__ b3) {
    int b = blockIdx.x, r = threadIdx.x;
    #pragma unroll
    for (int j = 0; j < 4; j++)
        out[(size_t)b * Rr + r + 256 * j] = b3[r + 256 * j];
}

__global__ __launch_bounds__(256)
void out_gemm_kernel(const float* __restrict__ W3, float* __restrict__ out) {
    __shared__ float As[Bb * 128];
    int rt = blockIdx.x * 128;
    int k0 = blockIdx.y * 128;
    int tid = threadIdx.x;

    #pragma unroll
    for (int l = 0; l < 32; l++) {
        int idx = tid + l * 256;
        int b = idx >> 7, k = idx & 127;
        As[b * 128 + k] = g_h2sum[(size_t)b * Hh + k0 + k] / g_cnt[b];
    }
    __syncthreads();

    int c = tid & 127, bg = tid >> 7;
    float acc[32];
    #pragma unroll
    for (int i = 0; i < 32; i++) acc[i] = 0.f;

    for (int k = 0; k < 128; k++) {
        float w = W3[(size_t)(k0 + k) * Rr + rt + c];
        #pragma unroll
        for (int i = 0; i < 32; i++)
            acc[i] += As[(bg * 32 + i) * 128 + k] * w;
    }
    #pragma unroll
    for (int i = 0; i < 32; i++)
        atomicAdd(&out[(size_t)(bg * 32 + i) * Rr + rt + c], acc[i]);
}

// ============================================================================
extern "C" void kernel_launch(void* const* d_in, const int* in_sizes, int n_in,
                              void* d_out, int out_size) {
    const float* x  = (const float*)d_in[0];
    const float* y  = (const float*)d_in[1];
    const void*  mk = d_in[2];
    const float* W1 = (const float*)d_in[3];
    const float* b1 = (const float*)d_in[4];
    const float* W2 = (const float*)d_in[5];
    const float* b2 = (const float*)d_in[6];
    const float* W3 = (const float*)d_in[7];
    const float* b3 = (const float*)d_in[8];
    float* out = (float*)d_out;

    detect_mask_kernel<<<1, 1>>>((const unsigned int*)mk);
    normalize_mask_kernel<<<Bb, Nn>>>(mk);
    gemm_kernel<true><<<dim3(Hh / BN, Tt / BM), 256>>>(x, y, W1, b1);
    gemm_kernel<false><<<dim3(Hh / BN, Tt / BM), 256>>>(nullptr, nullptr, W2, b2);
    out_init_kernel<<<Bb, 256>>>(out, b3);
    out_gemm_kernel<<<dim3(Rr / 128, Hh / 128), 256>>>(W3, out);
}